// round 8
// baseline (speedup 1.0000x reference)
#include <cuda_runtime.h>
#include <cstdint>
#include <math.h>

#define B_GRAPHS 512
#define N_NODES  128
#define F_OUT    256
#define HEADS    4
#define HID      64
#define M_TOT    (B_GRAPHS * N_NODES)   // 65536

__device__ float g_X[(size_t)M_TOT * F_OUT];
__device__ float g_Y[(size_t)M_TOT * F_OUT];
__device__ float g_Wt[3][256 * 256];

// ---------------------------------------------------------------------------
#define CP_ASYNC16(dst, src) \
    asm volatile("cp.async.cg.shared.global [%0], [%1], 16;" \
        :: "r"((uint32_t)(dst)), "l"(src) : "memory")
#define CP_COMMIT() asm volatile("cp.async.commit_group;" ::: "memory")
#define CP_WAIT1()  asm volatile("cp.async.wait_group 1;" ::: "memory")
#define CP_WAIT0()  asm volatile("cp.async.wait_group 0;" ::: "memory")

__device__ __forceinline__ uint32_t smem_to_u32(const void* p) {
    uint32_t a;
    asm("{ .reg .u64 t; cvta.to.shared.u64 t, %1; cvt.u32.u64 %0, t; }"
        : "=r"(a) : "l"(p));
    return a;
}

__device__ __forceinline__ uint32_t tf32r(float f) {
    uint32_t u;
    asm("cvt.rna.tf32.f32 %0, %1;" : "=r"(u) : "f"(f));
    return u;
}

__device__ __forceinline__ void ldsm_x4(
    uint32_t& r0, uint32_t& r1, uint32_t& r2, uint32_t& r3, uint32_t addr)
{
    asm volatile("ldmatrix.sync.aligned.m8n8.x4.shared.b16 {%0,%1,%2,%3}, [%4];"
        : "=r"(r0), "=r"(r1), "=r"(r2), "=r"(r3) : "r"(addr));
}

__device__ __forceinline__ void mma_tf32(
    float& d0, float& d1, float& d2, float& d3,
    uint32_t a0, uint32_t a1, uint32_t a2, uint32_t a3,
    uint32_t b0, uint32_t b1)
{
    asm volatile(
        "mma.sync.aligned.m16n8k8.row.col.f32.tf32.tf32.f32 "
        "{%0,%1,%2,%3}, {%4,%5,%6,%7}, {%8,%9}, {%0,%1,%2,%3};"
        : "+f"(d0), "+f"(d1), "+f"(d2), "+f"(d3)
        : "r"(a0), "r"(a1), "r"(a2), "r"(a3), "r"(b0), "r"(b1));
}

__device__ __forceinline__ float leaky(float a) {
    return (a >= 0.f) ? a : 0.2f * a;
}

// ---------------------------------------------------------------------------
__global__ __launch_bounds__(256) void round_x_kernel(
    const float* __restrict__ x, float* __restrict__ xr)
{
    int t = blockIdx.x * 256 + threadIdx.x;
    float4 v = ((const float4*)x)[t];
    uint4 o = make_uint4(tf32r(v.x), tf32r(v.y), tf32r(v.z), tf32r(v.w));
    ((uint4*)xr)[t] = o;
}

__global__ __launch_bounds__(256) void transpose_all_kernel(
    const float* __restrict__ W0, const float* __restrict__ W1,
    const float* __restrict__ W2, float* __restrict__ Wt)
{
    int t = blockIdx.x * 256 + threadIdx.x;
    uint32_t* o = (uint32_t*)Wt;
    if (t < 128 * 256) {
        int k = t >> 8, n = t & 255;
        o[(size_t)n * 128 + k] = tf32r(W0[t]);
    } else if (t < 128 * 256 + 256 * 256) {
        int t2 = t - 128 * 256;
        int k = t2 >> 8, n = t2 & 255;
        o[65536 + (size_t)n * 256 + k] = tf32r(W1[t2]);
    } else {
        int t3 = t - 128 * 256 - 256 * 256;
        int k = t3 >> 8, n = t3 & 255;
        o[131072 + (size_t)n * 256 + k] = tf32r(W2[t3]);
    }
}

// ===========================================================================
// Fused layer kernel. 512 thr, 2 CTAs/SM, ~88KB smem.
// Attention: register-resident softmax feeding MMA A-fragments directly.
// ===========================================================================
#define PSTR 132
#define OFF_SVP  3072                  // [4][128]
#define OFF_DVP  5120                  // [4][128]
#define OFF_QP   7168                  // [2][8][128] warp q partials
#define OFF_Q    15360                 // [2][128]
#define OFF_U    16384
#define AS_STG   18432                 // 128 rows * 144B
#define LAYER_SMEM (OFF_U + 4 * AS_STG)   // 90112 -> 2 CTAs/SM
// Ht [128][132] f32 (67584 B) overlaps the 4 stage buffers in U.

__global__ __launch_bounds__(512, 2) void layer_kernel(
    const float* __restrict__ A, const float* __restrict__ Wt,
    const float* __restrict__ att_src, const float* __restrict__ att_dst,
    const float* __restrict__ bias_g,
    float* __restrict__ X, float* __restrict__ out_final,
    int K, int last)
{
    extern __shared__ char sm[];
    uint32_t sb = smem_to_u32(sm);
    float* atts  = (float*)(sm);
    float* attd  = (float*)(sm + 1024);
    float* biass = (float*)(sm + 2048);
    float* svp   = (float*)(sm + OFF_SVP);
    float* dvp   = (float*)(sm + OFF_DVP);
    float* qpart = (float*)(sm + OFF_QP);
    float* qv    = (float*)(sm + OFF_Q);
    uint32_t* Htu = (uint32_t*)(sm + OFF_U);

    const int tid = threadIdx.x;
    const int warp = tid >> 5, lane = tid & 31;
    const int gid = lane >> 2, tig = lane & 3;
    const int wm = warp & 3, wn = warp >> 2;
    const int b = blockIdx.x, m0 = b * 128;
    const int t4 = lane >> 3, r8 = lane & 7;

    if (tid < 256) {
        atts[tid]  = att_src[tid];
        attd[tid]  = att_dst[tid];
        biass[tid] = bias_g[tid];
    }

    // GEMM ldmatrix offsets
    uint32_t aoff[2], boff[2];
#pragma unroll
    for (int mt = 0; mt < 2; mt++)
        aoff[mt] = (uint32_t)((wm * 32 + mt * 16 + (t4 & 1) * 8 + r8) * 144
                              + (t4 >> 1) * 16);
#pragma unroll
    for (int pr = 0; pr < 2; pr++)
        boff[pr] = (uint32_t)((wn * 32 + pr * 16 + (t4 >> 1) * 8 + r8) * 144
                              + (t4 & 1) * 16);
    // attention Ht B-frag base offset (per 16-col group: + pr*16*528)
    const uint32_t hoffA = (uint32_t)(((t4 >> 1) * 8 + r8) * (PSTR * 4)
                                      + (t4 & 1) * 16);

    const int NC = K >> 5;

#pragma unroll 1
    for (int nh = 0; nh < 2; nh++) {
        // ---------------- GEMM half: 128 x 128 ----------------
        float acc[2][4][4];
#pragma unroll
        for (int mt = 0; mt < 2; mt++)
#pragma unroll
            for (int nt = 0; nt < 4; nt++)
#pragma unroll
                for (int c = 0; c < 4; c++) acc[mt][nt][c] = 0.f;

        auto load_chunk = [&](int k0, int stage) {
            uint32_t ab = sb + OFF_U + stage * AS_STG;
            uint32_t bb = sb + OFF_U + 2 * AS_STG + stage * AS_STG;
#pragma unroll
            for (int i = 0; i < 2; i++) {
                int g = tid + i * 512;
                int row = g >> 3, c = g & 7;
                CP_ASYNC16(ab + row * 144 + c * 16,
                           A + (size_t)(m0 + row) * K + k0 + c * 4);
            }
#pragma unroll
            for (int i = 0; i < 2; i++) {
                int g = tid + i * 512;
                int row = g >> 3, c = g & 7;
                CP_ASYNC16(bb + row * 144 + c * 16,
                           Wt + (size_t)(nh * 128 + row) * K + k0 + c * 4);
            }
        };

        load_chunk(0, 0);
        CP_COMMIT();

        for (int c = 0; c < NC; c++) {
            if (c + 1 < NC) {
                load_chunk((c + 1) << 5, (c + 1) & 1);
                CP_COMMIT();
                CP_WAIT1();
            } else {
                CP_WAIT0();
            }
            __syncthreads();

            uint32_t as_b = sb + OFF_U + (c & 1) * AS_STG;
            uint32_t bs_b = sb + OFF_U + 2 * AS_STG + (c & 1) * AS_STG;
#pragma unroll
            for (int kk = 0; kk < 4; kk++) {
                uint32_t a[2][4];
#pragma unroll
                for (int mt = 0; mt < 2; mt++)
                    ldsm_x4(a[mt][0], a[mt][1], a[mt][2], a[mt][3],
                            as_b + aoff[mt] + kk * 32);
                uint32_t bf[4][2];
#pragma unroll
                for (int pr = 0; pr < 2; pr++)
                    ldsm_x4(bf[pr * 2][0], bf[pr * 2][1],
                            bf[pr * 2 + 1][0], bf[pr * 2 + 1][1],
                            bs_b + boff[pr] + kk * 32);
#pragma unroll
                for (int mt = 0; mt < 2; mt++)
#pragma unroll
                    for (int nt = 0; nt < 4; nt++)
                        mma_tf32(acc[mt][nt][0], acc[mt][nt][1],
                                 acc[mt][nt][2], acc[mt][nt][3],
                                 a[mt][0], a[mt][1], a[mt][2], a[mt][3],
                                 bf[nt][0], bf[nt][1]);
            }
            __syncthreads();
        }

        // ---------------- epilogue: Ht (transposed tf32) + score partials ---
        const int hl_w = wn >> 1;
#pragma unroll
        for (int mt = 0; mt < 2; mt++) {
#pragma unroll
            for (int h2 = 0; h2 < 2; h2++) {
                int rl = wm * 32 + mt * 16 + gid + 8 * h2;
                float s = 0.f, d = 0.f;
#pragma unroll
                for (int nt = 0; nt < 4; nt++) {
                    int cl = (wn & 1) * 32 + nt * 8 + tig * 2;
                    int gc = nh * 128 + wn * 32 + nt * 8 + tig * 2;
                    float v0 = acc[mt][nt][h2 * 2], v1 = acc[mt][nt][h2 * 2 + 1];
                    s = fmaf(v0, atts[gc], s);  s = fmaf(v1, atts[gc + 1], s);
                    d = fmaf(v0, attd[gc], d);  d = fmaf(v1, attd[gc + 1], d);
                    Htu[(hl_w * 64 + cl) * PSTR + rl]     = tf32r(v0);
                    Htu[(hl_w * 64 + cl + 1) * PSTR + rl] = tf32r(v1);
                }
                s += __shfl_xor_sync(0xffffffffu, s, 1);
                s += __shfl_xor_sync(0xffffffffu, s, 2);
                d += __shfl_xor_sync(0xffffffffu, d, 1);
                d += __shfl_xor_sync(0xffffffffu, d, 2);
                if (tig == 0) {
                    svp[wn * 128 + rl] = s;
                    dvp[wn * 128 + rl] = d;
                }
            }
        }
        __syncthreads();

        // ---------------- attention: 2 heads, register softmax ----------------
        // warp -> (hl = warp>>3, wm8 = warp&7); 16 rows x 64 cols per warp.
        {
            const int hl  = warp >> 3;
            const int wm8 = warp & 7;
            const int gh  = nh * 2 + hl;
            const uint32_t ht_b = sb + OFF_U + (uint32_t)hl * (64 * PSTR * 4);
            const float* svh = svp + hl * 256;
            const float* dvh = dvp + hl * 256;

            const int rr0 = wm8 * 16 + gid;
            const float dd0 = dvh[rr0] + dvh[128 + rr0];
            const float dd1 = dvh[rr0 + 8] + dvh[128 + rr0 + 8];

            // pre-pass: row max over this lane's 32 columns, reduce over tig
            float mx0 = -1e30f, mx1 = -1e30f;
#pragma unroll
            for (int t = 0; t < 32; t++) {
                int j = tig + 4 * t;
                float sj = svh[j] + svh[128 + j];
                mx0 = fmaxf(mx0, leaky(sj + dd0));
                mx1 = fmaxf(mx1, leaky(sj + dd1));
            }
            mx0 = fmaxf(mx0, __shfl_xor_sync(0xffffffffu, mx0, 1));
            mx0 = fmaxf(mx0, __shfl_xor_sync(0xffffffffu, mx0, 2));
            mx1 = fmaxf(mx1, __shfl_xor_sync(0xffffffffu, mx1, 1));
            mx1 = fmaxf(mx1, __shfl_xor_sync(0xffffffffu, mx1, 2));

            if (!last) {
                float oacc[8][4];
#pragma unroll
                for (int nt = 0; nt < 8; nt++)
#pragma unroll
                    for (int c = 0; c < 4; c++) oacc[nt][c] = 0.f;
                float sum0 = 0.f, sum1 = 0.f;

#pragma unroll
                for (int kk = 0; kk < 16; kk++) {
                    int j0 = kk * 8 + tig, j1 = j0 + 4;
                    float sj0 = svh[j0] + svh[128 + j0];
                    float sj1 = svh[j1] + svh[128 + j1];
                    float p00 = __expf(leaky(sj0 + dd0) - mx0);
                    float p10 = __expf(leaky(sj0 + dd1) - mx1);
                    float p01 = __expf(leaky(sj1 + dd0) - mx0);
                    float p11 = __expf(leaky(sj1 + dd1) - mx1);
                    sum0 += p00 + p01;
                    sum1 += p10 + p11;
                    uint32_t a0 = tf32r(p00), a1 = tf32r(p10);
                    uint32_t a2 = tf32r(p01), a3 = tf32r(p11);
#pragma unroll
                    for (int pr = 0; pr < 4; pr++) {
                        uint32_t b0, b1, b2, b3;
                        ldsm_x4(b0, b1, b2, b3,
                                ht_b + pr * (16 * PSTR * 4) + hoffA + kk * 32);
                        mma_tf32(oacc[pr * 2][0], oacc[pr * 2][1],
                                 oacc[pr * 2][2], oacc[pr * 2][3],
                                 a0, a1, a2, a3, b0, b1);
                        mma_tf32(oacc[pr * 2 + 1][0], oacc[pr * 2 + 1][1],
                                 oacc[pr * 2 + 1][2], oacc[pr * 2 + 1][3],
                                 a0, a1, a2, a3, b2, b3);
                    }
                }
                sum0 += __shfl_xor_sync(0xffffffffu, sum0, 1);
                sum0 += __shfl_xor_sync(0xffffffffu, sum0, 2);
                sum1 += __shfl_xor_sync(0xffffffffu, sum1, 1);
                sum1 += __shfl_xor_sync(0xffffffffu, sum1, 2);
                float inv0 = 1.0f / sum0, inv1 = 1.0f / sum1;

                float* o0 = X + ((size_t)m0 + rr0) * 256 + gh * 64;
                float* o1 = X + ((size_t)m0 + rr0 + 8) * 256 + gh * 64;
#pragma unroll
                for (int nt = 0; nt < 8; nt++) {
                    int col = nt * 8 + tig * 2;
                    float bb0 = biass[gh * 64 + col];
                    float bb1 = biass[gh * 64 + col + 1];
                    float2 v0 = make_float2(
                        __uint_as_float(tf32r(fmaf(oacc[nt][0], inv0, bb0))),
                        __uint_as_float(tf32r(fmaf(oacc[nt][1], inv0, bb1))));
                    float2 v1 = make_float2(
                        __uint_as_float(tf32r(fmaf(oacc[nt][2], inv1, bb0))),
                        __uint_as_float(tf32r(fmaf(oacc[nt][3], inv1, bb1))));
                    *(float2*)&o0[col] = v0;
                    *(float2*)&o1[col] = v1;
                }
            } else {
                // q path: q_j = sum_i e_ij / r_i ; no MMA
                float sum0 = 0.f, sum1 = 0.f;
#pragma unroll
                for (int t = 0; t < 32; t++) {
                    int j = tig + 4 * t;
                    float sj = svh[j] + svh[128 + j];
                    sum0 += __expf(leaky(sj + dd0) - mx0);
                    sum1 += __expf(leaky(sj + dd1) - mx1);
                }
                sum0 += __shfl_xor_sync(0xffffffffu, sum0, 1);
                sum0 += __shfl_xor_sync(0xffffffffu, sum0, 2);
                sum1 += __shfl_xor_sync(0xffffffffu, sum1, 1);
                sum1 += __shfl_xor_sync(0xffffffffu, sum1, 2);
                float inv0 = 1.0f / sum0, inv1 = 1.0f / sum1;

                float qa[32];
#pragma unroll
                for (int t = 0; t < 32; t++) {
                    int j = tig + 4 * t;
                    float sj = svh[j] + svh[128 + j];
                    qa[t] = __expf(leaky(sj + dd0) - mx0) * inv0
                          + __expf(leaky(sj + dd1) - mx1) * inv1;
                }
#pragma unroll
                for (int t = 0; t < 32; t++) {
                    qa[t] += __shfl_xor_sync(0xffffffffu, qa[t], 4);
                    qa[t] += __shfl_xor_sync(0xffffffffu, qa[t], 8);
                    qa[t] += __shfl_xor_sync(0xffffffffu, qa[t], 16);
                }
                if (gid == 0) {
#pragma unroll
                    for (int t = 0; t < 32; t++)
                        qpart[(hl * 8 + wm8) * 128 + tig + 4 * t] = qa[t];
                }
                __syncthreads();
                if (tid < 256) {
                    int hh = tid >> 7, cc = tid & 127;
                    float qs = 0.f;
#pragma unroll
                    for (int w = 0; w < 8; w++)
                        qs += qpart[(hh * 8 + w) * 128 + cc];
                    qv[hh * 128 + cc] = qs;
                }
                __syncthreads();
                // out = q^T Ht  (both heads of this half)
#pragma unroll 1
                for (int hq = 0; hq < 2; hq++) {
                    int c = tid >> 3, t8 = tid & 7;    // c: 0..63
                    float a3 = 0.f;
#pragma unroll 4
                    for (int jj = 0; jj < 16; jj++) {
                        int j = t8 * 16 + jj;
                        a3 += qv[hq * 128 + j] *
                              __uint_as_float(Htu[(hq * 64 + c) * PSTR + j]);
                    }
                    a3 += __shfl_xor_sync(0xffffffffu, a3, 1);
                    a3 += __shfl_xor_sync(0xffffffffu, a3, 2);
                    a3 += __shfl_xor_sync(0xffffffffu, a3, 4);
                    int gho = nh * 2 + hq;
                    if (t8 == 0)
                        out_final[(size_t)b * 256 + gho * 64 + c] =
                            a3 + 128.f * biass[gho * 64 + c];
                }
            }
        }
        __syncthreads();   // Ht dead; next half may overwrite staging
    } // nh
}

// ---------------------------------------------------------------------------
extern "C" void kernel_launch(void* const* d_in, const int* in_sizes, int n_in,
                              void* d_out, int out_size)
{
    const float* x = (const float*)d_in[0];
    const float* W[3]    = {(const float*)d_in[2], (const float*)d_in[6],  (const float*)d_in[10]};
    const float* asv[3]  = {(const float*)d_in[3], (const float*)d_in[7],  (const float*)d_in[11]};
    const float* adv[3]  = {(const float*)d_in[4], (const float*)d_in[8],  (const float*)d_in[12]};
    const float* bias[3] = {(const float*)d_in[5], (const float*)d_in[9],  (const float*)d_in[13]};

    float *pX, *pY, *pWt;
    cudaGetSymbolAddress((void**)&pX, g_X);
    cudaGetSymbolAddress((void**)&pY, g_Y);
    cudaGetSymbolAddress((void**)&pWt, g_Wt);

    cudaFuncSetAttribute(layer_kernel,
                         cudaFuncAttributeMaxDynamicSharedMemorySize, LAYER_SMEM);

    transpose_all_kernel<<<640, 256>>>(W[0], W[1], W[2], pWt);
    round_x_kernel<<<8192, 256>>>(x, pY);

    // layer 0: g_Y(xr) -> g_X ; layer 1: g_X -> g_Y ; layer 2: g_Y -> d_out
    const float* in_buf[3]  = {pY, pX, pY};
    float*       out_buf[3] = {pX, pY, nullptr};

    for (int l = 0; l < 3; l++) {
        const int K = (l == 0) ? 128 : 256;
        const float* Wtl = pWt + (size_t)l * 65536;
        layer_kernel<<<512, 512, LAYER_SMEM>>>(
            in_buf[l], Wtl, asv[l], adv[l], bias[l],
            out_buf[l], (float*)d_out, K, l == 2);
    }
}

// round 9
// speedup vs baseline: 1.2781x; 1.2781x over previous
#include <cuda_runtime.h>
#include <cstdint>
#include <math.h>

#define B_GRAPHS 512
#define N_NODES  128
#define F_OUT    256
#define HEADS    4
#define HID      64
#define M_TOT    (B_GRAPHS * N_NODES)   // 65536

__device__ float g_X[(size_t)M_TOT * F_OUT];
__device__ float g_Y[(size_t)M_TOT * F_OUT];
__device__ float g_Wt[3][256 * 256];

// ---------------------------------------------------------------------------
#define CP_ASYNC16(dst, src) \
    asm volatile("cp.async.cg.shared.global [%0], [%1], 16;" \
        :: "r"((uint32_t)(dst)), "l"(src) : "memory")
#define CP_COMMIT() asm volatile("cp.async.commit_group;" ::: "memory")
#define CP_WAIT1()  asm volatile("cp.async.wait_group 1;" ::: "memory")
#define CP_WAIT0()  asm volatile("cp.async.wait_group 0;" ::: "memory")

__device__ __forceinline__ uint32_t smem_to_u32(const void* p) {
    uint32_t a;
    asm("{ .reg .u64 t; cvta.to.shared.u64 t, %1; cvt.u32.u64 %0, t; }"
        : "=r"(a) : "l"(p));
    return a;
}

__device__ __forceinline__ uint32_t tf32r(float f) {
    uint32_t u;
    asm("cvt.rna.tf32.f32 %0, %1;" : "=r"(u) : "f"(f));
    return u;
}

__device__ __forceinline__ void ldsm_x4(
    uint32_t& r0, uint32_t& r1, uint32_t& r2, uint32_t& r3, uint32_t addr)
{
    asm volatile("ldmatrix.sync.aligned.m8n8.x4.shared.b16 {%0,%1,%2,%3}, [%4];"
        : "=r"(r0), "=r"(r1), "=r"(r2), "=r"(r3) : "r"(addr));
}

__device__ __forceinline__ void mma_tf32(
    float& d0, float& d1, float& d2, float& d3,
    uint32_t a0, uint32_t a1, uint32_t a2, uint32_t a3,
    uint32_t b0, uint32_t b1)
{
    asm volatile(
        "mma.sync.aligned.m16n8k8.row.col.f32.tf32.tf32.f32 "
        "{%0,%1,%2,%3}, {%4,%5,%6,%7}, {%8,%9}, {%0,%1,%2,%3};"
        : "+f"(d0), "+f"(d1), "+f"(d2), "+f"(d3)
        : "r"(a0), "r"(a1), "r"(a2), "r"(a3), "r"(b0), "r"(b1));
}

__device__ __forceinline__ float leaky(float a) {
    return (a >= 0.f) ? a : 0.2f * a;
}

// ---------------------------------------------------------------------------
__global__ __launch_bounds__(256) void round_x_kernel(
    const float* __restrict__ x, float* __restrict__ xr)
{
    int t = blockIdx.x * 256 + threadIdx.x;
    float4 v = ((const float4*)x)[t];
    uint4 o = make_uint4(tf32r(v.x), tf32r(v.y), tf32r(v.z), tf32r(v.w));
    ((uint4*)xr)[t] = o;
}

__global__ __launch_bounds__(256) void transpose_all_kernel(
    const float* __restrict__ W0, const float* __restrict__ W1,
    const float* __restrict__ W2, float* __restrict__ Wt)
{
    int t = blockIdx.x * 256 + threadIdx.x;
    uint32_t* o = (uint32_t*)Wt;
    if (t < 128 * 256) {
        int k = t >> 8, n = t & 255;
        o[(size_t)n * 128 + k] = tf32r(W0[t]);
    } else if (t < 128 * 256 + 256 * 256) {
        int t2 = t - 128 * 256;
        int k = t2 >> 8, n = t2 & 255;
        o[65536 + (size_t)n * 256 + k] = tf32r(W1[t2]);
    } else {
        int t3 = t - 128 * 256 - 256 * 256;
        int k = t3 >> 8, n = t3 & 255;
        o[131072 + (size_t)n * 256 + k] = tf32r(W2[t3]);
    }
}

// ===========================================================================
// Fused layer kernel. 512 thr, 2 CTAs/SM, 90KB smem.
// GEMM: R7 structure (proven). Attention: register softmax -> A-fragments,
// warp tile 16 rows x 32 cols, zero barriers, no P in smem.
// ===========================================================================
#define PSTR 132
#define OFF_SVP  3072                  // [4][128]
#define OFF_DVP  5120                  // [4][128]
#define OFF_QP   7168                  // [2][8][128]
#define OFF_Q    15360                 // [2][128]
#define OFF_U    16384
#define AS_STG   18432                 // 128 rows * 144B
#define LAYER_SMEM (OFF_U + 4 * AS_STG)   // 90112 -> 2 CTAs/SM
// Ht [128][132] f32 (67584 B) overlaps the 4 stage buffers in U.

__global__ __launch_bounds__(512, 2) void layer_kernel(
    const float* __restrict__ A, const float* __restrict__ Wt,
    const float* __restrict__ att_src, const float* __restrict__ att_dst,
    const float* __restrict__ bias_g,
    float* __restrict__ X, float* __restrict__ out_final,
    int K, int last)
{
    extern __shared__ char sm[];
    uint32_t sb = smem_to_u32(sm);
    float* atts  = (float*)(sm);
    float* attd  = (float*)(sm + 1024);
    float* biass = (float*)(sm + 2048);
    float* svp   = (float*)(sm + OFF_SVP);
    float* dvp   = (float*)(sm + OFF_DVP);
    float* qpart = (float*)(sm + OFF_QP);
    float* qv    = (float*)(sm + OFF_Q);
    uint32_t* Htu = (uint32_t*)(sm + OFF_U);

    const int tid = threadIdx.x;
    const int warp = tid >> 5, lane = tid & 31;
    const int gid = lane >> 2, tig = lane & 3;
    const int wm = warp & 3, wn = warp >> 2;
    const int b = blockIdx.x, m0 = b * 128;
    const int t4 = lane >> 3, r8 = lane & 7;

    if (tid < 256) {
        atts[tid]  = att_src[tid];
        attd[tid]  = att_dst[tid];
        biass[tid] = bias_g[tid];
    }

    // GEMM ldmatrix offsets
    uint32_t aoff[2], boff[2];
#pragma unroll
    for (int mt = 0; mt < 2; mt++)
        aoff[mt] = (uint32_t)((wm * 32 + mt * 16 + (t4 & 1) * 8 + r8) * 144
                              + (t4 >> 1) * 16);
#pragma unroll
    for (int pr = 0; pr < 2; pr++)
        boff[pr] = (uint32_t)((wn * 32 + pr * 16 + (t4 >> 1) * 8 + r8) * 144
                              + (t4 & 1) * 16);
    // attention: warp = (wm8 rows, wn2 col-group)
    const int wm8 = warp & 7, wn2 = warp >> 3;
    const uint32_t hoffA = (uint32_t)(((t4 >> 1) * 8 + r8) * (PSTR * 4)
                                      + (t4 & 1) * 16);

    const int NC = K >> 5;

#pragma unroll 1
    for (int nh = 0; nh < 2; nh++) {
        // ---------------- GEMM half: 128 x 128 ----------------
        float acc[2][4][4];
#pragma unroll
        for (int mt = 0; mt < 2; mt++)
#pragma unroll
            for (int nt = 0; nt < 4; nt++)
#pragma unroll
                for (int c = 0; c < 4; c++) acc[mt][nt][c] = 0.f;

        auto load_chunk = [&](int k0, int stage) {
            uint32_t ab = sb + OFF_U + stage * AS_STG;
            uint32_t bb = sb + OFF_U + 2 * AS_STG + stage * AS_STG;
#pragma unroll
            for (int i = 0; i < 2; i++) {
                int g = tid + i * 512;
                int row = g >> 3, c = g & 7;
                CP_ASYNC16(ab + row * 144 + c * 16,
                           A + (size_t)(m0 + row) * K + k0 + c * 4);
            }
#pragma unroll
            for (int i = 0; i < 2; i++) {
                int g = tid + i * 512;
                int row = g >> 3, c = g & 7;
                CP_ASYNC16(bb + row * 144 + c * 16,
                           Wt + (size_t)(nh * 128 + row) * K + k0 + c * 4);
            }
        };

        load_chunk(0, 0);
        CP_COMMIT();

        for (int c = 0; c < NC; c++) {
            if (c + 1 < NC) {
                load_chunk((c + 1) << 5, (c + 1) & 1);
                CP_COMMIT();
                CP_WAIT1();
            } else {
                CP_WAIT0();
            }
            __syncthreads();

            uint32_t as_b = sb + OFF_U + (c & 1) * AS_STG;
            uint32_t bs_b = sb + OFF_U + 2 * AS_STG + (c & 1) * AS_STG;
#pragma unroll
            for (int kk = 0; kk < 4; kk++) {
                uint32_t a[2][4];
#pragma unroll
                for (int mt = 0; mt < 2; mt++)
                    ldsm_x4(a[mt][0], a[mt][1], a[mt][2], a[mt][3],
                            as_b + aoff[mt] + kk * 32);
                uint32_t bf[4][2];
#pragma unroll
                for (int pr = 0; pr < 2; pr++)
                    ldsm_x4(bf[pr * 2][0], bf[pr * 2][1],
                            bf[pr * 2 + 1][0], bf[pr * 2 + 1][1],
                            bs_b + boff[pr] + kk * 32);
#pragma unroll
                for (int mt = 0; mt < 2; mt++)
#pragma unroll
                    for (int nt = 0; nt < 4; nt++)
                        mma_tf32(acc[mt][nt][0], acc[mt][nt][1],
                                 acc[mt][nt][2], acc[mt][nt][3],
                                 a[mt][0], a[mt][1], a[mt][2], a[mt][3],
                                 bf[nt][0], bf[nt][1]);
            }
            __syncthreads();
        }

        // ---------------- epilogue: Ht (transposed tf32) + score partials ---
        const int hl_w = wn >> 1;
#pragma unroll
        for (int mt = 0; mt < 2; mt++) {
#pragma unroll
            for (int h2 = 0; h2 < 2; h2++) {
                int rl = wm * 32 + mt * 16 + gid + 8 * h2;
                float s = 0.f, d = 0.f;
#pragma unroll
                for (int nt = 0; nt < 4; nt++) {
                    int cl = (wn & 1) * 32 + nt * 8 + tig * 2;
                    int gc = nh * 128 + wn * 32 + nt * 8 + tig * 2;
                    float v0 = acc[mt][nt][h2 * 2], v1 = acc[mt][nt][h2 * 2 + 1];
                    s = fmaf(v0, atts[gc], s);  s = fmaf(v1, atts[gc + 1], s);
                    d = fmaf(v0, attd[gc], d);  d = fmaf(v1, attd[gc + 1], d);
                    Htu[(hl_w * 64 + cl) * PSTR + rl]     = tf32r(v0);
                    Htu[(hl_w * 64 + cl + 1) * PSTR + rl] = tf32r(v1);
                }
                s += __shfl_xor_sync(0xffffffffu, s, 1);
                s += __shfl_xor_sync(0xffffffffu, s, 2);
                d += __shfl_xor_sync(0xffffffffu, d, 1);
                d += __shfl_xor_sync(0xffffffffu, d, 2);
                if (tig == 0) {
                    svp[wn * 128 + rl] = s;
                    dvp[wn * 128 + rl] = d;
                }
            }
        }
        __syncthreads();

        // ---------------- attention: loop heads; 16x32 warp tiles ----------
#pragma unroll 1
        for (int hl = 0; hl < 2; hl++) {
            const int gh = nh * 2 + hl;
            const uint32_t ht_b = sb + OFF_U + (uint32_t)hl * (64 * PSTR * 4)
                                  + (uint32_t)(wn2 * 32) * (PSTR * 4);
            const float* svh = svp + hl * 256;
            const float* dvh = dvp + hl * 256;

            const int rr0 = wm8 * 16 + gid;
            const float dd0 = dvh[rr0] + dvh[128 + rr0];
            const float dd1 = dvh[rr0 + 8] + dvh[128 + rr0 + 8];

            // row-max over this lane's 32 cols, reduced over tig
            float mx0 = -1e30f, mx1 = -1e30f;
#pragma unroll
            for (int t = 0; t < 32; t++) {
                int j = tig + 4 * t;
                float sj = svh[j] + svh[128 + j];
                mx0 = fmaxf(mx0, leaky(sj + dd0));
                mx1 = fmaxf(mx1, leaky(sj + dd1));
            }
            mx0 = fmaxf(mx0, __shfl_xor_sync(0xffffffffu, mx0, 1));
            mx0 = fmaxf(mx0, __shfl_xor_sync(0xffffffffu, mx0, 2));
            mx1 = fmaxf(mx1, __shfl_xor_sync(0xffffffffu, mx1, 1));
            mx1 = fmaxf(mx1, __shfl_xor_sync(0xffffffffu, mx1, 2));

            if (!last) {
                float oacc[4][4];
#pragma unroll
                for (int nt = 0; nt < 4; nt++)
#pragma unroll
                    for (int c = 0; c < 4; c++) oacc[nt][c] = 0.f;
                float sum0 = 0.f, sum1 = 0.f;

#pragma unroll
                for (int kk = 0; kk < 16; kk++) {
                    int j0 = kk * 8 + tig, j1 = j0 + 4;
                    float sj0 = svh[j0] + svh[128 + j0];
                    float sj1 = svh[j1] + svh[128 + j1];
                    float p00 = __expf(leaky(sj0 + dd0) - mx0);
                    float p10 = __expf(leaky(sj0 + dd1) - mx1);
                    float p01 = __expf(leaky(sj1 + dd0) - mx0);
                    float p11 = __expf(leaky(sj1 + dd1) - mx1);
                    sum0 += p00 + p01;
                    sum1 += p10 + p11;
                    uint32_t a0 = tf32r(p00), a1 = tf32r(p10);
                    uint32_t a2 = tf32r(p01), a3 = tf32r(p11);
#pragma unroll
                    for (int pr = 0; pr < 2; pr++) {
                        uint32_t b0, b1, b2, b3;
                        ldsm_x4(b0, b1, b2, b3,
                                ht_b + pr * (16 * PSTR * 4) + hoffA + kk * 32);
                        mma_tf32(oacc[pr * 2][0], oacc[pr * 2][1],
                                 oacc[pr * 2][2], oacc[pr * 2][3],
                                 a0, a1, a2, a3, b0, b1);
                        mma_tf32(oacc[pr * 2 + 1][0], oacc[pr * 2 + 1][1],
                                 oacc[pr * 2 + 1][2], oacc[pr * 2 + 1][3],
                                 a0, a1, a2, a3, b2, b3);
                    }
                }
                sum0 += __shfl_xor_sync(0xffffffffu, sum0, 1);
                sum0 += __shfl_xor_sync(0xffffffffu, sum0, 2);
                sum1 += __shfl_xor_sync(0xffffffffu, sum1, 1);
                sum1 += __shfl_xor_sync(0xffffffffu, sum1, 2);
                float inv0 = 1.0f / sum0, inv1 = 1.0f / sum1;

                float* o0 = X + ((size_t)m0 + rr0) * 256 + gh * 64;
                float* o1 = X + ((size_t)m0 + rr0 + 8) * 256 + gh * 64;
#pragma unroll
                for (int nt = 0; nt < 4; nt++) {
                    int col = wn2 * 32 + nt * 8 + tig * 2;
                    float bb0 = biass[gh * 64 + col];
                    float bb1 = biass[gh * 64 + col + 1];
                    float2 v0 = make_float2(
                        __uint_as_float(tf32r(fmaf(oacc[nt][0], inv0, bb0))),
                        __uint_as_float(tf32r(fmaf(oacc[nt][1], inv0, bb1))));
                    float2 v1 = make_float2(
                        __uint_as_float(tf32r(fmaf(oacc[nt][2], inv1, bb0))),
                        __uint_as_float(tf32r(fmaf(oacc[nt][3], inv1, bb1))));
                    *(float2*)&o0[col] = v0;
                    *(float2*)&o1[col] = v1;
                }
            } else {
                // q path: q_j = sum_i e_ij / r_i (no MMA)
                float sum0 = 0.f, sum1 = 0.f;
#pragma unroll
                for (int t = 0; t < 32; t++) {
                    int j = tig + 4 * t;
                    float sj = svh[j] + svh[128 + j];
                    sum0 += __expf(leaky(sj + dd0) - mx0);
                    sum1 += __expf(leaky(sj + dd1) - mx1);
                }
                sum0 += __shfl_xor_sync(0xffffffffu, sum0, 1);
                sum0 += __shfl_xor_sync(0xffffffffu, sum0, 2);
                sum1 += __shfl_xor_sync(0xffffffffu, sum1, 1);
                sum1 += __shfl_xor_sync(0xffffffffu, sum1, 2);
                float inv0 = 1.0f / sum0, inv1 = 1.0f / sum1;

                // per-column partial over this warp's 16 rows, no array
                if (wn2 == 0) {
#pragma unroll
                    for (int t = 0; t < 32; t++) {
                        int j = tig + 4 * t;
                        float sj = svh[j] + svh[128 + j];
                        float qc = __expf(leaky(sj + dd0) - mx0) * inv0
                                 + __expf(leaky(sj + dd1) - mx1) * inv1;
                        qc += __shfl_xor_sync(0xffffffffu, qc, 4);
                        qc += __shfl_xor_sync(0xffffffffu, qc, 8);
                        qc += __shfl_xor_sync(0xffffffffu, qc, 16);
                        if (gid == 0)
                            qpart[(hl * 8 + wm8) * 128 + j] = qc;
                    }
                }
            }
        } // hl

        if (last) {
            __syncthreads();
            if (tid < 256) {
                int hh = tid >> 7, cc = tid & 127;
                float qs = 0.f;
#pragma unroll
                for (int w = 0; w < 8; w++)
                    qs += qpart[(hh * 8 + w) * 128 + cc];
                qv[hh * 128 + cc] = qs;
            }
            __syncthreads();
#pragma unroll 1
            for (int hq = 0; hq < 2; hq++) {
                int c = tid >> 3, t8 = tid & 7;
                float a3 = 0.f;
#pragma unroll 4
                for (int jj = 0; jj < 16; jj++) {
                    int j = t8 * 16 + jj;
                    a3 += qv[hq * 128 + j] *
                          __uint_as_float(Htu[(hq * 64 + c) * PSTR + j]);
                }
                a3 += __shfl_xor_sync(0xffffffffu, a3, 1);
                a3 += __shfl_xor_sync(0xffffffffu, a3, 2);
                a3 += __shfl_xor_sync(0xffffffffu, a3, 4);
                int gho = nh * 2 + hq;
                if (t8 == 0)
                    out_final[(size_t)b * 256 + gho * 64 + c] =
                        a3 + 128.f * biass[gho * 64 + c];
            }
        }
        __syncthreads();   // Ht dead; next half may overwrite staging
    } // nh
}

// ---------------------------------------------------------------------------
extern "C" void kernel_launch(void* const* d_in, const int* in_sizes, int n_in,
                              void* d_out, int out_size)
{
    const float* x = (const float*)d_in[0];
    const float* W[3]    = {(const float*)d_in[2], (const float*)d_in[6],  (const float*)d_in[10]};
    const float* asv[3]  = {(const float*)d_in[3], (const float*)d_in[7],  (const float*)d_in[11]};
    const float* adv[3]  = {(const float*)d_in[4], (const float*)d_in[8],  (const float*)d_in[12]};
    const float* bias[3] = {(const float*)d_in[5], (const float*)d_in[9],  (const float*)d_in[13]};

    float *pX, *pY, *pWt;
    cudaGetSymbolAddress((void**)&pX, g_X);
    cudaGetSymbolAddress((void**)&pY, g_Y);
    cudaGetSymbolAddress((void**)&pWt, g_Wt);

    cudaFuncSetAttribute(layer_kernel,
                         cudaFuncAttributeMaxDynamicSharedMemorySize, LAYER_SMEM);

    transpose_all_kernel<<<640, 256>>>(W[0], W[1], W[2], pWt);
    round_x_kernel<<<8192, 256>>>(x, pY);

    const float* in_buf[3]  = {pY, pX, pY};
    float*       out_buf[3] = {pX, pY, nullptr};

    for (int l = 0; l < 3; l++) {
        const int K = (l == 0) ? 128 : 256;
        const float* Wtl = pWt + (size_t)l * 65536;
        layer_kernel<<<512, 512, LAYER_SMEM>>>(
            in_buf[l], Wtl, asv[l], adv[l], bias[l],
            out_buf[l], (float*)d_out, K, l == 2);
    }
}

// round 10
// speedup vs baseline: 1.4815x; 1.1592x over previous
#include <cuda_runtime.h>
#include <cstdint>
#include <math.h>

#define B_GRAPHS 512
#define N_NODES  128
#define F_OUT    256
#define HEADS    4
#define HID      64
#define M_TOT    (B_GRAPHS * N_NODES)   // 65536

__device__ float g_X[(size_t)M_TOT * F_OUT];
__device__ float g_Y[(size_t)M_TOT * F_OUT];
__device__ float g_Wt[3][256 * 256];

// ---------------------------------------------------------------------------
#define CP_ASYNC16(dst, src) \
    asm volatile("cp.async.cg.shared.global [%0], [%1], 16;" \
        :: "r"((uint32_t)(dst)), "l"(src) : "memory")
#define CP_COMMIT() asm volatile("cp.async.commit_group;" ::: "memory")
#define CP_WAIT1()  asm volatile("cp.async.wait_group 1;" ::: "memory")
#define CP_WAIT0()  asm volatile("cp.async.wait_group 0;" ::: "memory")

__device__ __forceinline__ uint32_t smem_to_u32(const void* p) {
    uint32_t a;
    asm("{ .reg .u64 t; cvta.to.shared.u64 t, %1; cvt.u32.u64 %0, t; }"
        : "=r"(a) : "l"(p));
    return a;
}

__device__ __forceinline__ uint32_t tf32r(float f) {
    uint32_t u;
    asm("cvt.rna.tf32.f32 %0, %1;" : "=r"(u) : "f"(f));
    return u;
}

__device__ __forceinline__ void ldsm_x4(
    uint32_t& r0, uint32_t& r1, uint32_t& r2, uint32_t& r3, uint32_t addr)
{
    asm volatile("ldmatrix.sync.aligned.m8n8.x4.shared.b16 {%0,%1,%2,%3}, [%4];"
        : "=r"(r0), "=r"(r1), "=r"(r2), "=r"(r3) : "r"(addr));
}

__device__ __forceinline__ void mma_tf32(
    float& d0, float& d1, float& d2, float& d3,
    uint32_t a0, uint32_t a1, uint32_t a2, uint32_t a3,
    uint32_t b0, uint32_t b1)
{
    asm volatile(
        "mma.sync.aligned.m16n8k8.row.col.f32.tf32.tf32.f32 "
        "{%0,%1,%2,%3}, {%4,%5,%6,%7}, {%8,%9}, {%0,%1,%2,%3};"
        : "+f"(d0), "+f"(d1), "+f"(d2), "+f"(d3)
        : "r"(a0), "r"(a1), "r"(a2), "r"(a3), "r"(b0), "r"(b1));
}

__device__ __forceinline__ float leaky(float a) {
    return (a >= 0.f) ? a : 0.2f * a;
}

// ---------------------------------------------------------------------------
__global__ __launch_bounds__(256) void round_x_kernel(
    const float* __restrict__ x, float* __restrict__ xr)
{
    int t = blockIdx.x * 256 + threadIdx.x;
    float4 v = ((const float4*)x)[t];
    uint4 o = make_uint4(tf32r(v.x), tf32r(v.y), tf32r(v.z), tf32r(v.w));
    ((uint4*)xr)[t] = o;
}

__global__ __launch_bounds__(256) void transpose_all_kernel(
    const float* __restrict__ W0, const float* __restrict__ W1,
    const float* __restrict__ W2, float* __restrict__ Wt)
{
    int t = blockIdx.x * 256 + threadIdx.x;
    uint32_t* o = (uint32_t*)Wt;
    if (t < 128 * 256) {
        int k = t >> 8, n = t & 255;
        o[(size_t)n * 128 + k] = tf32r(W0[t]);
    } else if (t < 128 * 256 + 256 * 256) {
        int t2 = t - 128 * 256;
        int k = t2 >> 8, n = t2 & 255;
        o[65536 + (size_t)n * 256 + k] = tf32r(W1[t2]);
    } else {
        int t3 = t - 128 * 256 - 256 * 256;
        int k = t3 >> 8, n = t3 & 255;
        o[131072 + (size_t)n * 256 + k] = tf32r(W2[t3]);
    }
}

// ===========================================================================
// Fused layer kernel. 512 thr, 2 CTAs/SM, ~91KB smem.
// Attention: register softmax -> A-fragments; row max = leaky(smax + d_i)
// (exact, since leaky is monotone), so no max pre-pass at all.
// ===========================================================================
#define PSTR 132
#define OFF_SVP  3072                  // [4][128] partials
#define OFF_DVP  5120
#define OFF_SV   7168                  // [2][128] reduced
#define OFF_DV   8192
#define OFF_SMX  9216                  // [2] head score max
#define OFF_QP   9472                  // [2][8][128]
#define OFF_QV   17664                 // [2][128]
#define OFF_U    18944
#define AS_STG   18432                 // 128 rows * 144B
#define LAYER_SMEM (OFF_U + 4 * AS_STG)   // 92672 -> 2 CTAs/SM
// Ht [128][132] f32 (67584 B) overlaps the 4 stage buffers in U.

__global__ __launch_bounds__(512, 2) void layer_kernel(
    const float* __restrict__ A, const float* __restrict__ Wt,
    const float* __restrict__ att_src, const float* __restrict__ att_dst,
    const float* __restrict__ bias_g,
    float* __restrict__ X, float* __restrict__ out_final,
    int K, int last)
{
    extern __shared__ char sm[];
    uint32_t sb = smem_to_u32(sm);
    float* atts  = (float*)(sm);
    float* attd  = (float*)(sm + 1024);
    float* biass = (float*)(sm + 2048);
    float* svp   = (float*)(sm + OFF_SVP);
    float* dvp   = (float*)(sm + OFF_DVP);
    float* sv    = (float*)(sm + OFF_SV);
    float* dv    = (float*)(sm + OFF_DV);
    float* smaxs = (float*)(sm + OFF_SMX);
    float* qpart = (float*)(sm + OFF_QP);
    float* qv    = (float*)(sm + OFF_QV);
    uint32_t* Htu = (uint32_t*)(sm + OFF_U);

    const int tid = threadIdx.x;
    const int warp = tid >> 5, lane = tid & 31;
    const int gid = lane >> 2, tig = lane & 3;
    const int wm = warp & 3, wn = warp >> 2;
    const int b = blockIdx.x, m0 = b * 128;
    const int t4 = lane >> 3, r8 = lane & 7;

    if (tid < 256) {
        atts[tid]  = att_src[tid];
        attd[tid]  = att_dst[tid];
        biass[tid] = bias_g[tid];
    }

    // GEMM ldmatrix offsets
    uint32_t aoff[2], boff[2];
#pragma unroll
    for (int mt = 0; mt < 2; mt++)
        aoff[mt] = (uint32_t)((wm * 32 + mt * 16 + (t4 & 1) * 8 + r8) * 144
                              + (t4 >> 1) * 16);
#pragma unroll
    for (int pr = 0; pr < 2; pr++)
        boff[pr] = (uint32_t)((wn * 32 + pr * 16 + (t4 >> 1) * 8 + r8) * 144
                              + (t4 & 1) * 16);
    // attention: warp = (wm8 rows, wn2 col-group)
    const int wm8 = warp & 7, wn2 = warp >> 3;
    const uint32_t hoffA = (uint32_t)(((t4 >> 1) * 8 + r8) * (PSTR * 4)
                                      + (t4 & 1) * 16);

    const int NC = K >> 5;

#pragma unroll 1
    for (int nh = 0; nh < 2; nh++) {
        // ---------------- GEMM half: 128 x 128 ----------------
        float acc[2][4][4];
#pragma unroll
        for (int mt = 0; mt < 2; mt++)
#pragma unroll
            for (int nt = 0; nt < 4; nt++)
#pragma unroll
                for (int c = 0; c < 4; c++) acc[mt][nt][c] = 0.f;

        auto load_chunk = [&](int k0, int stage) {
            uint32_t ab = sb + OFF_U + stage * AS_STG;
            uint32_t bb = sb + OFF_U + 2 * AS_STG + stage * AS_STG;
#pragma unroll
            for (int i = 0; i < 2; i++) {
                int g = tid + i * 512;
                int row = g >> 3, c = g & 7;
                CP_ASYNC16(ab + row * 144 + c * 16,
                           A + (size_t)(m0 + row) * K + k0 + c * 4);
            }
#pragma unroll
            for (int i = 0; i < 2; i++) {
                int g = tid + i * 512;
                int row = g >> 3, c = g & 7;
                CP_ASYNC16(bb + row * 144 + c * 16,
                           Wt + (size_t)(nh * 128 + row) * K + k0 + c * 4);
            }
        };

        load_chunk(0, 0);
        CP_COMMIT();

        for (int c = 0; c < NC; c++) {
            if (c + 1 < NC) {
                load_chunk((c + 1) << 5, (c + 1) & 1);
                CP_COMMIT();
                CP_WAIT1();
            } else {
                CP_WAIT0();
            }
            __syncthreads();

            uint32_t as_b = sb + OFF_U + (c & 1) * AS_STG;
            uint32_t bs_b = sb + OFF_U + 2 * AS_STG + (c & 1) * AS_STG;
#pragma unroll
            for (int kk = 0; kk < 4; kk++) {
                uint32_t a[2][4];
#pragma unroll
                for (int mt = 0; mt < 2; mt++)
                    ldsm_x4(a[mt][0], a[mt][1], a[mt][2], a[mt][3],
                            as_b + aoff[mt] + kk * 32);
                uint32_t bf[4][2];
#pragma unroll
                for (int pr = 0; pr < 2; pr++)
                    ldsm_x4(bf[pr * 2][0], bf[pr * 2][1],
                            bf[pr * 2 + 1][0], bf[pr * 2 + 1][1],
                            bs_b + boff[pr] + kk * 32);
#pragma unroll
                for (int mt = 0; mt < 2; mt++)
#pragma unroll
                    for (int nt = 0; nt < 4; nt++)
                        mma_tf32(acc[mt][nt][0], acc[mt][nt][1],
                                 acc[mt][nt][2], acc[mt][nt][3],
                                 a[mt][0], a[mt][1], a[mt][2], a[mt][3],
                                 bf[nt][0], bf[nt][1]);
            }
            __syncthreads();
        }

        // ---------------- epilogue: Ht (transposed tf32) + score partials ---
        const int hl_w = wn >> 1;
#pragma unroll
        for (int mt = 0; mt < 2; mt++) {
#pragma unroll
            for (int h2 = 0; h2 < 2; h2++) {
                int rl = wm * 32 + mt * 16 + gid + 8 * h2;
                float s = 0.f, d = 0.f;
#pragma unroll
                for (int nt = 0; nt < 4; nt++) {
                    int cl = (wn & 1) * 32 + nt * 8 + tig * 2;
                    int gc = nh * 128 + wn * 32 + nt * 8 + tig * 2;
                    float v0 = acc[mt][nt][h2 * 2], v1 = acc[mt][nt][h2 * 2 + 1];
                    s = fmaf(v0, atts[gc], s);  s = fmaf(v1, atts[gc + 1], s);
                    d = fmaf(v0, attd[gc], d);  d = fmaf(v1, attd[gc + 1], d);
                    Htu[(hl_w * 64 + cl) * PSTR + rl]     = tf32r(v0);
                    Htu[(hl_w * 64 + cl + 1) * PSTR + rl] = tf32r(v1);
                }
                s += __shfl_xor_sync(0xffffffffu, s, 1);
                s += __shfl_xor_sync(0xffffffffu, s, 2);
                d += __shfl_xor_sync(0xffffffffu, d, 1);
                d += __shfl_xor_sync(0xffffffffu, d, 2);
                if (tig == 0) {
                    svp[wn * 128 + rl] = s;
                    dvp[wn * 128 + rl] = d;
                }
            }
        }
        __syncthreads();

        // reduce partials -> sv/dv; head-wide score max -> smaxs
        if (tid < 256) {
            int hh = tid >> 7, j = tid & 127;
            sv[hh * 128 + j] = svp[(2 * hh) * 128 + j]
                             + svp[(2 * hh + 1) * 128 + j];
            dv[hh * 128 + j] = dvp[(2 * hh) * 128 + j]
                             + dvp[(2 * hh + 1) * 128 + j];
        } else if (tid < 320) {
            int t = tid - 256, hh = t >> 5, l = t & 31;
            float m = -1e30f;
#pragma unroll
            for (int q = 0; q < 4; q++) {
                int j = l + q * 32;
                m = fmaxf(m, svp[(2 * hh) * 128 + j]
                             + svp[(2 * hh + 1) * 128 + j]);
            }
#pragma unroll
            for (int off = 16; off; off >>= 1)
                m = fmaxf(m, __shfl_xor_sync(0xffffffffu, m, off));
            if (l == 0) smaxs[hh] = m;
        }
        __syncthreads();

        // ---------------- attention: loop heads; 16x32 warp tiles ----------
#pragma unroll 1
        for (int hl = 0; hl < 2; hl++) {
            const int gh = nh * 2 + hl;
            const uint32_t ht_b = sb + OFF_U + (uint32_t)hl * (64 * PSTR * 4)
                                  + (uint32_t)(wn2 * 32) * (PSTR * 4);
            const float* svh = sv + hl * 128;

            const int rr0 = wm8 * 16 + gid;
            const float dd0 = dv[hl * 128 + rr0];
            const float dd1 = dv[hl * 128 + rr0 + 8];
            const float smx = smaxs[hl];
            // exact row max: leaky is monotone increasing
            const float mx0 = leaky(smx + dd0);
            const float mx1 = leaky(smx + dd1);

            if (!last) {
                float oacc[4][4];
#pragma unroll
                for (int nt = 0; nt < 4; nt++)
#pragma unroll
                    for (int c = 0; c < 4; c++) oacc[nt][c] = 0.f;
                float sum0 = 0.f, sum1 = 0.f;

#pragma unroll
                for (int kk = 0; kk < 16; kk++) {
                    int j0 = kk * 8 + tig, j1 = j0 + 4;
                    float sj0 = svh[j0], sj1 = svh[j1];
                    float p00 = __expf(leaky(sj0 + dd0) - mx0);
                    float p10 = __expf(leaky(sj0 + dd1) - mx1);
                    float p01 = __expf(leaky(sj1 + dd0) - mx0);
                    float p11 = __expf(leaky(sj1 + dd1) - mx1);
                    sum0 += p00 + p01;
                    sum1 += p10 + p11;
                    uint32_t a0 = tf32r(p00), a1 = tf32r(p10);
                    uint32_t a2 = tf32r(p01), a3 = tf32r(p11);
#pragma unroll
                    for (int pr = 0; pr < 2; pr++) {
                        uint32_t b0, b1, b2, b3;
                        ldsm_x4(b0, b1, b2, b3,
                                ht_b + pr * (16 * PSTR * 4) + hoffA + kk * 32);
                        mma_tf32(oacc[pr * 2][0], oacc[pr * 2][1],
                                 oacc[pr * 2][2], oacc[pr * 2][3],
                                 a0, a1, a2, a3, b0, b1);
                        mma_tf32(oacc[pr * 2 + 1][0], oacc[pr * 2 + 1][1],
                                 oacc[pr * 2 + 1][2], oacc[pr * 2 + 1][3],
                                 a0, a1, a2, a3, b2, b3);
                    }
                }
                sum0 += __shfl_xor_sync(0xffffffffu, sum0, 1);
                sum0 += __shfl_xor_sync(0xffffffffu, sum0, 2);
                sum1 += __shfl_xor_sync(0xffffffffu, sum1, 1);
                sum1 += __shfl_xor_sync(0xffffffffu, sum1, 2);
                float inv0 = 1.0f / sum0, inv1 = 1.0f / sum1;

                float* o0 = X + ((size_t)m0 + rr0) * 256 + gh * 64;
                float* o1 = X + ((size_t)m0 + rr0 + 8) * 256 + gh * 64;
#pragma unroll
                for (int nt = 0; nt < 4; nt++) {
                    int col = wn2 * 32 + nt * 8 + tig * 2;
                    float bb0 = biass[gh * 64 + col];
                    float bb1 = biass[gh * 64 + col + 1];
                    float2 v0 = make_float2(
                        __uint_as_float(tf32r(fmaf(oacc[nt][0], inv0, bb0))),
                        __uint_as_float(tf32r(fmaf(oacc[nt][1], inv0, bb1))));
                    float2 v1 = make_float2(
                        __uint_as_float(tf32r(fmaf(oacc[nt][2], inv1, bb0))),
                        __uint_as_float(tf32r(fmaf(oacc[nt][3], inv1, bb1))));
                    *(float2*)&o0[col] = v0;
                    *(float2*)&o1[col] = v1;
                }
            } else {
                // q path: q_j = sum_i e_ij / r_i (no MMA)
                float sum0 = 0.f, sum1 = 0.f;
#pragma unroll
                for (int t = 0; t < 32; t++) {
                    int j = tig + 4 * t;
                    float sj = svh[j];
                    sum0 += __expf(leaky(sj + dd0) - mx0);
                    sum1 += __expf(leaky(sj + dd1) - mx1);
                }
                sum0 += __shfl_xor_sync(0xffffffffu, sum0, 1);
                sum0 += __shfl_xor_sync(0xffffffffu, sum0, 2);
                sum1 += __shfl_xor_sync(0xffffffffu, sum1, 1);
                sum1 += __shfl_xor_sync(0xffffffffu, sum1, 2);
                float inv0 = 1.0f / sum0, inv1 = 1.0f / sum1;

                if (wn2 == 0) {
#pragma unroll
                    for (int t = 0; t < 32; t++) {
                        int j = tig + 4 * t;
                        float sj = svh[j];
                        float qc = __expf(leaky(sj + dd0) - mx0) * inv0
                                 + __expf(leaky(sj + dd1) - mx1) * inv1;
                        qc += __shfl_xor_sync(0xffffffffu, qc, 4);
                        qc += __shfl_xor_sync(0xffffffffu, qc, 8);
                        qc += __shfl_xor_sync(0xffffffffu, qc, 16);
                        if (gid == 0)
                            qpart[(hl * 8 + wm8) * 128 + j] = qc;
                    }
                }
            }
        } // hl

        if (last) {
            __syncthreads();
            if (tid < 256) {
                int hh = tid >> 7, cc = tid & 127;
                float qs = 0.f;
#pragma unroll
                for (int w = 0; w < 8; w++)
                    qs += qpart[(hh * 8 + w) * 128 + cc];
                qv[hh * 128 + cc] = qs;
            }
            __syncthreads();
#pragma unroll 1
            for (int hq = 0; hq < 2; hq++) {
                int c = tid >> 3, t8 = tid & 7;
                float a3 = 0.f;
#pragma unroll 4
                for (int jj = 0; jj < 16; jj++) {
                    int j = t8 * 16 + jj;
                    a3 += qv[hq * 128 + j] *
                          __uint_as_float(Htu[(hq * 64 + c) * PSTR + j]);
                }
                a3 += __shfl_xor_sync(0xffffffffu, a3, 1);
                a3 += __shfl_xor_sync(0xffffffffu, a3, 2);
                a3 += __shfl_xor_sync(0xffffffffu, a3, 4);
                int gho = nh * 2 + hq;
                if (t8 == 0)
                    out_final[(size_t)b * 256 + gho * 64 + c] =
                        a3 + 128.f * biass[gho * 64 + c];
            }
        }
        __syncthreads();   // Ht dead; next half may overwrite staging
    } // nh
}

// ---------------------------------------------------------------------------
extern "C" void kernel_launch(void* const* d_in, const int* in_sizes, int n_in,
                              void* d_out, int out_size)
{
    const float* x = (const float*)d_in[0];
    const float* W[3]    = {(const float*)d_in[2], (const float*)d_in[6],  (const float*)d_in[10]};
    const float* asv[3]  = {(const float*)d_in[3], (const float*)d_in[7],  (const float*)d_in[11]};
    const float* adv[3]  = {(const float*)d_in[4], (const float*)d_in[8],  (const float*)d_in[12]};
    const float* bias[3] = {(const float*)d_in[5], (const float*)d_in[9],  (const float*)d_in[13]};

    float *pX, *pY, *pWt;
    cudaGetSymbolAddress((void**)&pX, g_X);
    cudaGetSymbolAddress((void**)&pY, g_Y);
    cudaGetSymbolAddress((void**)&pWt, g_Wt);

    cudaFuncSetAttribute(layer_kernel,
                         cudaFuncAttributeMaxDynamicSharedMemorySize, LAYER_SMEM);

    transpose_all_kernel<<<640, 256>>>(W[0], W[1], W[2], pWt);
    round_x_kernel<<<8192, 256>>>(x, pY);

    const float* in_buf[3]  = {pY, pX, pY};
    float*       out_buf[3] = {pX, pY, nullptr};

    for (int l = 0; l < 3; l++) {
        const int K = (l == 0) ? 128 : 256;
        const float* Wtl = pWt + (size_t)l * 65536;
        layer_kernel<<<512, 512, LAYER_SMEM>>>(
            in_buf[l], Wtl, asv[l], adv[l], bias[l],
            out_buf[l], (float*)d_out, K, l == 2);
    }
}

// round 11
// speedup vs baseline: 1.7919x; 1.2095x over previous
#include <cuda_runtime.h>
#include <cstdint>
#include <math.h>

#define B_GRAPHS 512
#define N_NODES  128
#define F_OUT    256
#define HEADS    4
#define HID      64
#define M_TOT    (B_GRAPHS * N_NODES)   // 65536
#define LOG2E    1.4426950408889634f

__device__ float g_X[(size_t)M_TOT * F_OUT];
__device__ float g_Y[(size_t)M_TOT * F_OUT];
__device__ float g_Wt[3][256 * 256];

// ---------------------------------------------------------------------------
#define CP_ASYNC16(dst, src) \
    asm volatile("cp.async.cg.shared.global [%0], [%1], 16;" \
        :: "r"((uint32_t)(dst)), "l"(src) : "memory")
#define CP_COMMIT() asm volatile("cp.async.commit_group;" ::: "memory")
#define CP_WAIT1()  asm volatile("cp.async.wait_group 1;" ::: "memory")
#define CP_WAIT0()  asm volatile("cp.async.wait_group 0;" ::: "memory")

__device__ __forceinline__ uint32_t smem_to_u32(const void* p) {
    uint32_t a;
    asm("{ .reg .u64 t; cvta.to.shared.u64 t, %1; cvt.u32.u64 %0, t; }"
        : "=r"(a) : "l"(p));
    return a;
}

__device__ __forceinline__ uint32_t tf32r(float f) {
    uint32_t u;
    asm("cvt.rna.tf32.f32 %0, %1;" : "=r"(u) : "f"(f));
    return u;
}

__device__ __forceinline__ float ex2(float x) {
    float r;
    asm("ex2.approx.f32 %0, %1;" : "=f"(r) : "f"(x));
    return r;
}

__device__ __forceinline__ void ldsm_x4(
    uint32_t& r0, uint32_t& r1, uint32_t& r2, uint32_t& r3, uint32_t addr)
{
    asm volatile("ldmatrix.sync.aligned.m8n8.x4.shared.b16 {%0,%1,%2,%3}, [%4];"
        : "=r"(r0), "=r"(r1), "=r"(r2), "=r"(r3) : "r"(addr));
}

__device__ __forceinline__ void mma_tf32(
    float& d0, float& d1, float& d2, float& d3,
    uint32_t a0, uint32_t a1, uint32_t a2, uint32_t a3,
    uint32_t b0, uint32_t b1)
{
    asm volatile(
        "mma.sync.aligned.m16n8k8.row.col.f32.tf32.tf32.f32 "
        "{%0,%1,%2,%3}, {%4,%5,%6,%7}, {%8,%9}, {%0,%1,%2,%3};"
        : "+f"(d0), "+f"(d1), "+f"(d2), "+f"(d3)
        : "r"(a0), "r"(a1), "r"(a2), "r"(a3), "r"(b0), "r"(b1));
}

__device__ __forceinline__ float leaky(float a) {
    return (a >= 0.f) ? a : 0.2f * a;
}

// ---------------------------------------------------------------------------
__global__ __launch_bounds__(256) void round_x_kernel(
    const float* __restrict__ x, float* __restrict__ xr)
{
    int t = blockIdx.x * 256 + threadIdx.x;
    float4 v = ((const float4*)x)[t];
    uint4 o = make_uint4(tf32r(v.x), tf32r(v.y), tf32r(v.z), tf32r(v.w));
    ((uint4*)xr)[t] = o;
}

__global__ __launch_bounds__(256) void transpose_all_kernel(
    const float* __restrict__ W0, const float* __restrict__ W1,
    const float* __restrict__ W2, float* __restrict__ Wt)
{
    int t = blockIdx.x * 256 + threadIdx.x;
    uint32_t* o = (uint32_t*)Wt;
    if (t < 128 * 256) {
        int k = t >> 8, n = t & 255;
        o[(size_t)n * 128 + k] = tf32r(W0[t]);
    } else if (t < 128 * 256 + 256 * 256) {
        int t2 = t - 128 * 256;
        int k = t2 >> 8, n = t2 & 255;
        o[65536 + (size_t)n * 256 + k] = tf32r(W1[t2]);
    } else {
        int t3 = t - 128 * 256 - 256 * 256;
        int k = t3 >> 8, n = t3 & 255;
        o[131072 + (size_t)n * 256 + k] = tf32r(W2[t3]);
    }
}

// ===========================================================================
// Fused layer kernel. 512 thr, 2 CTAs/SM.
// Attention: one warp = (head, 16-row group) x 64 cols; every exp computed
// once; ex2 with log2e-prescaled scores; exact row max via leaky monotonicity.
// ===========================================================================
#define PSTR 132
#define OFF_SVP  3072                  // [4][128] partials
#define OFF_DVP  5120
#define OFF_SVI  7168                  // float2 [2][16][4] interleaved scores
#define OFF_DV   8192                  // [2][128] scaled
#define OFF_SMX  9216                  // [2]
#define OFF_QP   9472                  // [16][128]
#define OFF_QV   17664                 // [2][128]
#define OFF_U    18944
#define AS_STG   18432                 // 128 rows * 144B
#define LAYER_SMEM (OFF_U + 4 * AS_STG)   // 92672 -> 2 CTAs/SM
// Ht [128][132] f32 (67584 B) overlaps the 4 stage buffers in U.

__global__ __launch_bounds__(512, 2) void layer_kernel(
    const float* __restrict__ A, const float* __restrict__ Wt,
    const float* __restrict__ att_src, const float* __restrict__ att_dst,
    const float* __restrict__ bias_g,
    float* __restrict__ X, float* __restrict__ out_final,
    int K, int last)
{
    extern __shared__ char sm[];
    uint32_t sb = smem_to_u32(sm);
    float* atts  = (float*)(sm);
    float* attd  = (float*)(sm + 1024);
    float* biass = (float*)(sm + 2048);
    float* svp   = (float*)(sm + OFF_SVP);
    float* dvp   = (float*)(sm + OFF_DVP);
    float2* svI  = (float2*)(sm + OFF_SVI);
    float* dv    = (float*)(sm + OFF_DV);
    float* smaxs = (float*)(sm + OFF_SMX);
    float* qpart = (float*)(sm + OFF_QP);
    float* qv    = (float*)(sm + OFF_QV);
    uint32_t* Htu = (uint32_t*)(sm + OFF_U);

    const int tid = threadIdx.x;
    const int warp = tid >> 5, lane = tid & 31;
    const int gid = lane >> 2, tig = lane & 3;
    const int wm = warp & 3, wn = warp >> 2;
    const int b = blockIdx.x, m0 = b * 128;
    const int t4 = lane >> 3, r8 = lane & 7;

    if (tid < 256) {
        atts[tid]  = att_src[tid];
        attd[tid]  = att_dst[tid];
        biass[tid] = bias_g[tid];
    }

    // GEMM ldmatrix offsets
    uint32_t aoff[2], boff[2];
#pragma unroll
    for (int mt = 0; mt < 2; mt++)
        aoff[mt] = (uint32_t)((wm * 32 + mt * 16 + (t4 & 1) * 8 + r8) * 144
                              + (t4 >> 1) * 16);
#pragma unroll
    for (int pr = 0; pr < 2; pr++)
        boff[pr] = (uint32_t)((wn * 32 + pr * 16 + (t4 >> 1) * 8 + r8) * 144
                              + (t4 & 1) * 16);
    // attention: warp = (hl head, wm8 row-group); 16 rows x 64 cols
    const int wm8 = warp & 7, hl = warp >> 3;
    const uint32_t hoffA = (uint32_t)(((t4 >> 1) * 8 + r8) * (PSTR * 4)
                                      + (t4 & 1) * 16);

    const int NC = K >> 5;

#pragma unroll 1
    for (int nh = 0; nh < 2; nh++) {
        // ---------------- GEMM half: 128 x 128 ----------------
        float acc[2][4][4];
#pragma unroll
        for (int mt = 0; mt < 2; mt++)
#pragma unroll
            for (int nt = 0; nt < 4; nt++)
#pragma unroll
                for (int c = 0; c < 4; c++) acc[mt][nt][c] = 0.f;

        auto load_chunk = [&](int k0, int stage) {
            uint32_t ab = sb + OFF_U + stage * AS_STG;
            uint32_t bb = sb + OFF_U + 2 * AS_STG + stage * AS_STG;
#pragma unroll
            for (int i = 0; i < 2; i++) {
                int g = tid + i * 512;
                int row = g >> 3, c = g & 7;
                CP_ASYNC16(ab + row * 144 + c * 16,
                           A + (size_t)(m0 + row) * K + k0 + c * 4);
            }
#pragma unroll
            for (int i = 0; i < 2; i++) {
                int g = tid + i * 512;
                int row = g >> 3, c = g & 7;
                CP_ASYNC16(bb + row * 144 + c * 16,
                           Wt + (size_t)(nh * 128 + row) * K + k0 + c * 4);
            }
        };

        load_chunk(0, 0);
        CP_COMMIT();

        for (int c = 0; c < NC; c++) {
            if (c + 1 < NC) {
                load_chunk((c + 1) << 5, (c + 1) & 1);
                CP_COMMIT();
                CP_WAIT1();
            } else {
                CP_WAIT0();
            }
            __syncthreads();

            uint32_t as_b = sb + OFF_U + (c & 1) * AS_STG;
            uint32_t bs_b = sb + OFF_U + 2 * AS_STG + (c & 1) * AS_STG;
#pragma unroll
            for (int kk = 0; kk < 4; kk++) {
                uint32_t a[2][4];
#pragma unroll
                for (int mt = 0; mt < 2; mt++)
                    ldsm_x4(a[mt][0], a[mt][1], a[mt][2], a[mt][3],
                            as_b + aoff[mt] + kk * 32);
                uint32_t bf[4][2];
#pragma unroll
                for (int pr = 0; pr < 2; pr++)
                    ldsm_x4(bf[pr * 2][0], bf[pr * 2][1],
                            bf[pr * 2 + 1][0], bf[pr * 2 + 1][1],
                            bs_b + boff[pr] + kk * 32);
#pragma unroll
                for (int mt = 0; mt < 2; mt++)
#pragma unroll
                    for (int nt = 0; nt < 4; nt++)
                        mma_tf32(acc[mt][nt][0], acc[mt][nt][1],
                                 acc[mt][nt][2], acc[mt][nt][3],
                                 a[mt][0], a[mt][1], a[mt][2], a[mt][3],
                                 bf[nt][0], bf[nt][1]);
            }
            __syncthreads();
        }

        // ---------------- epilogue: Ht (transposed tf32) + score partials ---
        const int hl_w = wn >> 1;
#pragma unroll
        for (int mt = 0; mt < 2; mt++) {
#pragma unroll
            for (int h2 = 0; h2 < 2; h2++) {
                int rl = wm * 32 + mt * 16 + gid + 8 * h2;
                float s = 0.f, d = 0.f;
#pragma unroll
                for (int nt = 0; nt < 4; nt++) {
                    int cl = (wn & 1) * 32 + nt * 8 + tig * 2;
                    int gc = nh * 128 + wn * 32 + nt * 8 + tig * 2;
                    float v0 = acc[mt][nt][h2 * 2], v1 = acc[mt][nt][h2 * 2 + 1];
                    s = fmaf(v0, atts[gc], s);  s = fmaf(v1, atts[gc + 1], s);
                    d = fmaf(v0, attd[gc], d);  d = fmaf(v1, attd[gc + 1], d);
                    Htu[(hl_w * 64 + cl) * PSTR + rl]     = tf32r(v0);
                    Htu[(hl_w * 64 + cl + 1) * PSTR + rl] = tf32r(v1);
                }
                s += __shfl_xor_sync(0xffffffffu, s, 1);
                s += __shfl_xor_sync(0xffffffffu, s, 2);
                d += __shfl_xor_sync(0xffffffffu, d, 1);
                d += __shfl_xor_sync(0xffffffffu, d, 2);
                if (tig == 0) {
                    svp[wn * 128 + rl] = s;
                    dvp[wn * 128 + rl] = d;
                }
            }
        }
        __syncthreads();

        // reduce partials (scaled by log2e) -> svI (interleaved) / dv / smaxs
        if (tid < 256) {
            int hh = tid >> 7, j = tid & 127;
            float s2 = (svp[(2 * hh) * 128 + j]
                        + svp[(2 * hh + 1) * 128 + j]) * LOG2E;
            float d2 = (dvp[(2 * hh) * 128 + j]
                        + dvp[(2 * hh + 1) * 128 + j]) * LOG2E;
            dv[hh * 128 + j] = d2;
            int kk = j >> 3, r = j & 7;
            ((float*)svI)[((hh * 16 + kk) * 4 + (r & 3)) * 2 + (r >> 2)] = s2;
        } else if (tid < 320) {
            int t = tid - 256, hh = t >> 5, l = t & 31;
            float m = -1e30f;
#pragma unroll
            for (int q = 0; q < 4; q++) {
                int j = l + q * 32;
                m = fmaxf(m, svp[(2 * hh) * 128 + j]
                             + svp[(2 * hh + 1) * 128 + j]);
            }
#pragma unroll
            for (int off = 16; off; off >>= 1)
                m = fmaxf(m, __shfl_xor_sync(0xffffffffu, m, off));
            if (l == 0) smaxs[hh] = m * LOG2E;
        }
        __syncthreads();

        // ---------------- attention: 16x64 warp tiles, exp once ------------
        {
            const int gh = nh * 2 + hl;
            const uint32_t ht_b = sb + OFF_U + (uint32_t)hl * (64 * PSTR * 4);
            const float2* svh = svI + hl * 64;   // [kk][tig]

            const int rr0 = wm8 * 16 + gid;
            const float dd0 = dv[hl * 128 + rr0];
            const float dd1 = dv[hl * 128 + rr0 + 8];
            const float smx = smaxs[hl];
            const float mx0 = leaky(smx + dd0);   // exact row max (monotone)
            const float mx1 = leaky(smx + dd1);

            if (!last) {
                float oacc[8][4];
#pragma unroll
                for (int nt = 0; nt < 8; nt++)
#pragma unroll
                    for (int c = 0; c < 4; c++) oacc[nt][c] = 0.f;
                float sum0 = 0.f, sum1 = 0.f;

#pragma unroll
                for (int kk = 0; kk < 16; kk++) {
                    float2 sj = svh[kk * 4 + tig];
                    float p00 = ex2(leaky(sj.x + dd0) - mx0);
                    float p10 = ex2(leaky(sj.x + dd1) - mx1);
                    float p01 = ex2(leaky(sj.y + dd0) - mx0);
                    float p11 = ex2(leaky(sj.y + dd1) - mx1);
                    sum0 += p00 + p01;
                    sum1 += p10 + p11;
                    uint32_t a0 = tf32r(p00), a1 = tf32r(p10);
                    uint32_t a2 = tf32r(p01), a3 = tf32r(p11);
#pragma unroll
                    for (int pr = 0; pr < 4; pr++) {
                        uint32_t b0, b1, b2, b3;
                        ldsm_x4(b0, b1, b2, b3,
                                ht_b + pr * (16 * PSTR * 4) + hoffA + kk * 32);
                        mma_tf32(oacc[pr * 2][0], oacc[pr * 2][1],
                                 oacc[pr * 2][2], oacc[pr * 2][3],
                                 a0, a1, a2, a3, b0, b1);
                        mma_tf32(oacc[pr * 2 + 1][0], oacc[pr * 2 + 1][1],
                                 oacc[pr * 2 + 1][2], oacc[pr * 2 + 1][3],
                                 a0, a1, a2, a3, b2, b3);
                    }
                }
                sum0 += __shfl_xor_sync(0xffffffffu, sum0, 1);
                sum0 += __shfl_xor_sync(0xffffffffu, sum0, 2);
                sum1 += __shfl_xor_sync(0xffffffffu, sum1, 1);
                sum1 += __shfl_xor_sync(0xffffffffu, sum1, 2);
                float inv0 = 1.0f / sum0, inv1 = 1.0f / sum1;

                float* o0 = X + ((size_t)m0 + rr0) * 256 + gh * 64;
                float* o1 = X + ((size_t)m0 + rr0 + 8) * 256 + gh * 64;
#pragma unroll
                for (int nt = 0; nt < 8; nt++) {
                    int col = nt * 8 + tig * 2;
                    float bb0 = biass[gh * 64 + col];
                    float bb1 = biass[gh * 64 + col + 1];
                    float2 v0 = make_float2(
                        __uint_as_float(tf32r(fmaf(oacc[nt][0], inv0, bb0))),
                        __uint_as_float(tf32r(fmaf(oacc[nt][1], inv0, bb1))));
                    float2 v1 = make_float2(
                        __uint_as_float(tf32r(fmaf(oacc[nt][2], inv1, bb0))),
                        __uint_as_float(tf32r(fmaf(oacc[nt][3], inv1, bb1))));
                    *(float2*)&o0[col] = v0;
                    *(float2*)&o1[col] = v1;
                }
            } else {
                // q path: q_j = sum_i e_ij / r_i (no MMA)
                float sum0 = 0.f, sum1 = 0.f;
#pragma unroll
                for (int kk = 0; kk < 16; kk++) {
                    float2 sj = svh[kk * 4 + tig];
                    sum0 += ex2(leaky(sj.x + dd0) - mx0)
                          + ex2(leaky(sj.y + dd0) - mx0);
                    sum1 += ex2(leaky(sj.x + dd1) - mx1)
                          + ex2(leaky(sj.y + dd1) - mx1);
                }
                sum0 += __shfl_xor_sync(0xffffffffu, sum0, 1);
                sum0 += __shfl_xor_sync(0xffffffffu, sum0, 2);
                sum1 += __shfl_xor_sync(0xffffffffu, sum1, 1);
                sum1 += __shfl_xor_sync(0xffffffffu, sum1, 2);
                float inv0 = 1.0f / sum0, inv1 = 1.0f / sum1;

#pragma unroll
                for (int kk = 0; kk < 16; kk++) {
                    float2 sj = svh[kk * 4 + tig];
                    float qc0 = ex2(leaky(sj.x + dd0) - mx0) * inv0
                              + ex2(leaky(sj.x + dd1) - mx1) * inv1;
                    float qc1 = ex2(leaky(sj.y + dd0) - mx0) * inv0
                              + ex2(leaky(sj.y + dd1) - mx1) * inv1;
                    qc0 += __shfl_xor_sync(0xffffffffu, qc0, 4);
                    qc0 += __shfl_xor_sync(0xffffffffu, qc0, 8);
                    qc0 += __shfl_xor_sync(0xffffffffu, qc0, 16);
                    qc1 += __shfl_xor_sync(0xffffffffu, qc1, 4);
                    qc1 += __shfl_xor_sync(0xffffffffu, qc1, 8);
                    qc1 += __shfl_xor_sync(0xffffffffu, qc1, 16);
                    if (gid == 0) {
                        qpart[(hl * 8 + wm8) * 128 + kk * 8 + tig]     = qc0;
                        qpart[(hl * 8 + wm8) * 128 + kk * 8 + tig + 4] = qc1;
                    }
                }
            }
        }

        if (last) {
            __syncthreads();
            if (tid < 256) {
                int hh = tid >> 7, cc = tid & 127;
                float qs = 0.f;
#pragma unroll
                for (int w = 0; w < 8; w++)
                    qs += qpart[(hh * 8 + w) * 128 + cc];
                qv[hh * 128 + cc] = qs;
            }
            __syncthreads();
#pragma unroll 1
            for (int hq = 0; hq < 2; hq++) {
                int c = tid >> 3, t8 = tid & 7;
                float a3 = 0.f;
#pragma unroll 4
                for (int jj = 0; jj < 16; jj++) {
                    int j = t8 * 16 + jj;
                    a3 += qv[hq * 128 + j] *
                          __uint_as_float(Htu[(hq * 64 + c) * PSTR + j]);
                }
                a3 += __shfl_xor_sync(0xffffffffu, a3, 1);
                a3 += __shfl_xor_sync(0xffffffffu, a3, 2);
                a3 += __shfl_xor_sync(0xffffffffu, a3, 4);
                int gho = nh * 2 + hq;
                if (t8 == 0)
                    out_final[(size_t)b * 256 + gho * 64 + c] =
                        a3 + 128.f * biass[gho * 64 + c];
            }
        }
        __syncthreads();   // Ht dead; next half may overwrite staging
    } // nh
}

// ---------------------------------------------------------------------------
extern "C" void kernel_launch(void* const* d_in, const int* in_sizes, int n_in,
                              void* d_out, int out_size)
{
    const float* x = (const float*)d_in[0];
    const float* W[3]    = {(const float*)d_in[2], (const float*)d_in[6],  (const float*)d_in[10]};
    const float* asv[3]  = {(const float*)d_in[3], (const float*)d_in[7],  (const float*)d_in[11]};
    const float* adv[3]  = {(const float*)d_in[4], (const float*)d_in[8],  (const float*)d_in[12]};
    const float* bias[3] = {(const float*)d_in[5], (const float*)d_in[9],  (const float*)d_in[13]};

    float *pX, *pY, *pWt;
    cudaGetSymbolAddress((void**)&pX, g_X);
    cudaGetSymbolAddress((void**)&pY, g_Y);
    cudaGetSymbolAddress((void**)&pWt, g_Wt);

    cudaFuncSetAttribute(layer_kernel,
                         cudaFuncAttributeMaxDynamicSharedMemorySize, LAYER_SMEM);

    transpose_all_kernel<<<640, 256>>>(W[0], W[1], W[2], pWt);
    round_x_kernel<<<8192, 256>>>(x, pY);

    const float* in_buf[3]  = {pY, pX, pY};
    float*       out_buf[3] = {pX, pY, nullptr};

    for (int l = 0; l < 3; l++) {
        const int K = (l == 0) ? 128 : 256;
        const float* Wtl = pWt + (size_t)l * 65536;
        layer_kernel<<<512, 512, LAYER_SMEM>>>(
            in_buf[l], Wtl, asv[l], adv[l], bias[l],
            out_buf[l], (float*)d_out, K, l == 2);
    }
}